// round 8
// baseline (speedup 1.0000x reference)
#include <cuda_runtime.h>
#include <math.h>
#include <stdint.h>

#define NB    128
#define ND    32
#define NPAIR 16384
#define EPS2  0.25f
#define EPS4  0.0625f
#define PERC  111                        // pairs per CTA (ceil(16384/148))
#define RECF4 33                         // float4s per pair record
#define RECB  (RECF4*16)                 // 528 bytes
#define SRECB (PERC*RECB)                // 58608 B coefficient region
#define REDSL 33                         // u64 per lane in reduction buffer
#define REDB  (8*32*REDSL*8)             // 67584 B reduction region (8 slots)
#define SMEMT (SRECB + REDB)             // 126192 B total dynamic smem

typedef unsigned long long u64;

// ---------------- packed f32x2 helpers ---------------------------------------
__device__ __forceinline__ u64 pack2(float lo, float hi) {
    u64 r; asm("mov.b64 %0,{%1,%2};" : "=l"(r) : "f"(lo), "f"(hi)); return r;
}
__device__ __forceinline__ void unpack2(u64 v, float& lo, float& hi) {
    asm("mov.b64 {%0,%1},%2;" : "=f"(lo), "=f"(hi) : "l"(v));
}
__device__ __forceinline__ u64 fma2(u64 a, u64 b, u64 c) {
    u64 d; asm("fma.rn.f32x2 %0,%1,%2,%3;" : "=l"(d) : "l"(a), "l"(b), "l"(c)); return d;
}
__device__ __forceinline__ u64 add2(u64 a, u64 b) {
    u64 d; asm("add.rn.f32x2 %0,%1,%2;" : "=l"(d) : "l"(a), "l"(b)); return d;
}
__device__ __forceinline__ void lds_v2u64(uint32_t addr, u64& a, u64& b) {
    asm volatile("ld.shared.v2.u64 {%0,%1},[%2];" : "=l"(a), "=l"(b) : "r"(addr));
}
__device__ __forceinline__ uint32_t smem_u32(const void* p) {
    uint32_t a;
    asm("{ .reg .u64 t; cvta.to.shared.u64 t, %1; cvt.u32.u64 %0, t; }" : "=r"(a) : "l"(p));
    return a;
}
__device__ __forceinline__ void redg_f32(float* p, float v) {
    asm volatile("red.global.add.f32 [%0],%1;" :: "l"(p), "f"(v) : "memory");
}

// ---------------- device state ------------------------------------------------
// g_sum[b][0..31]=sum W*K, [32..63]=sum W*A, [64]=den. Zero at load; the last
// CTA of every launch re-zeroes it, preserving the invariant across replays.
__device__ float    g_sum[NB * 65];
__device__ unsigned g_ctr;

// ---------------- fused kernel ------------------------------------------------
// grid 148, 512 threads, 1 CTA/SM. CTA gx owns pairs [gx*PERC, gx*PERC+cnt).
// 16 warps = 4 batch-groups (32 batches each) x 4 pair slices.
// Phase A: compute coefficient records for the chunk into smem (once chip-wide).
// Phase B: hot loop (LDS + packed f32x2 FMA).
// Phase C: STS.64 tree reduction (no smem atomics) -> REDG -> last-CTA finalize.
__global__ void __launch_bounds__(512, 1)
kfused(const float* __restrict__ X,
       const float* __restrict__ tptr,
       const float* __restrict__ Mu0,
       const float* __restrict__ Mu1,
       const float* __restrict__ S0,
       const float* __restrict__ S1,
       const float* __restrict__ Lam,
       float* __restrict__ out) {
    extern __shared__ __align__(16) float4 srec[];
    __shared__ unsigned sLast;

    const int tid  = threadIdx.x;
    const int lane = tid & 31;
    const int w    = tid >> 5;
    const int gx   = blockIdx.x;

    const int pbeg = gx * PERC;
    const int cnt  = min(PERC, NPAIR - pbeg);

    // ---------------- Phase A: inline coefficient prep (lane = dim) ----------
    {
        const float t = tptr[0];
        const float u = 1.f - t;
        const int n = lane;
        for (int local = w; local < cnt; local += 16) {
            int p = pbeg + local;
            int i = p >> 7, j = p & 127;

            float s0 = S0[i * ND + n];
            float s1 = S1[j * ND + n];
            float Ds = sqrtf(fmaf(4.f * s0, s1, EPS4));
            float Cs = 0.5f * (Ds - EPS2);
            float Sigma = u * u * s0 + t * t * s1 + 2.f * t * u * Cs + EPS2 * t * u;
            float St = (t * s1 + u * Cs) - (u * s0 + t * Cs) - EPS2 * t;

            float inv = __fdividef(1.0f, Sigma);
            float K   = St * inv;

            float m0  = Mu0[i * ND + n];
            float m1  = Mu1[j * ND + n];
            float Mut = fmaf(t, m1, u * m0);
            float v   = m1 - m0;

            float a  = -0.5f * inv;
            float bq = Mut * inv;
            float A  = fmaf(-K, Mut, v);

            float cterm = fmaf(a * Mut, Mut, -0.5f * __logf(Sigma));
            #pragma unroll
            for (int o = 16; o; o >>= 1)
                cterm += __shfl_xor_sync(0xffffffffu, cterm, o);

            float aP = __shfl_xor_sync(0xffffffffu, a, 1);
            float bP = __shfl_xor_sync(0xffffffffu, bq, 1);
            float KP = __shfl_xor_sync(0xffffffffu, K, 1);
            float AP = __shfl_xor_sync(0xffffffffu, A, 1);

            float4* r4 = srec + local * RECF4;
            int k = n >> 1;
            if ((n & 1) == 0) r4[k]      = make_float4(a, aP, bq, bP);
            else              r4[16 + k] = make_float4(KP, K, AP, A);
            if (n == 0)       r4[32]     = make_float4(cterm, __ldg(Lam + p), 0.f, 0.f);
        }
    }
    __syncthreads();

    // ---------------- Phase B: hot loop ---------------------------------------
    const int group = w >> 2;                   // 0..3: 32-batch group
    const int slice = w & 3;                    // pair slice among 4 warps
    const int b     = group * 32 + lane;
    const uint32_t sbase = smem_u32(srec);

    u64 xp[16];
    {
        const float4* X4 = reinterpret_cast<const float4*>(X + b * ND);
        #pragma unroll
        for (int q = 0; q < 8; q++) {
            float4 xv = X4[q];
            xp[2 * q]     = pack2(xv.x, xv.y);
            xp[2 * q + 1] = pack2(xv.z, xv.w);
        }
    }
    u64 skp[16], sap[16];
    const u64 zz = pack2(0.f, 0.f);
    #pragma unroll
    for (int k = 0; k < 16; k++) { skp[k] = zz; sap[k] = zz; }
    float den = 0.f;

    for (int j = slice; j < cnt; j += 4) {
        uint32_t rec = sbase + j * RECB;

        u64 lw0 = zz, lw1 = zz;
        #pragma unroll
        for (int k = 0; k < 16; k += 2) {
            u64 ap, bp;
            lds_v2u64(rec + k * 16, ap, bp);
            lw0 = fma2(xp[k], fma2(ap, xp[k], bp), lw0);
            u64 ap1, bp1;
            lds_v2u64(rec + (k + 1) * 16, ap1, bp1);
            lw1 = fma2(xp[k + 1], fma2(ap1, xp[k + 1], bp1), lw1);
        }
        float cl0, cl1;
        asm volatile("ld.shared.v2.f32 {%0,%1},[%2];"
                     : "=f"(cl0), "=f"(cl1) : "r"(rec + 512));
        float a0, a1, b0v, b1v;
        unpack2(lw0, a0, a1);
        unpack2(lw1, b0v, b1v);
        float lw = (a0 + a1) + (b0v + b1v) + cl0;
        lw = fminf(fmaxf(lw, -50.f), 50.f);
        float wt = __expf(lw) * cl1;
        den += wt;
        u64 wtp = pack2(wt, wt);

        #pragma unroll
        for (int k = 0; k < 16; k++) {
            u64 kp, Ap;
            lds_v2u64(rec + 256 + k * 16, kp, Ap);
            skp[k] = fma2(wtp, kp, skp[k]);
            sap[k] = fma2(wtp, Ap, sap[k]);
        }
    }

    // ---------------- Phase C: tree reduction (no smem atomics) ---------------
    __syncthreads();                            // done reading coefficients
    u64* redbuf = reinterpret_cast<u64*>(reinterpret_cast<char*>(srec) + SRECB);

    // round 1: slices 1 & 3 store; slices 0 & 2 absorb
    if (slice & 1) {
        u64* dst = redbuf + ((group * 2 + (slice >> 1)) * 32 + lane) * REDSL;
        #pragma unroll
        for (int k = 0; k < 16; k++) { dst[k] = skp[k]; dst[16 + k] = sap[k]; }
        dst[32] = pack2(den, 0.f);
    }
    __syncthreads();
    if ((slice & 1) == 0) {
        u64* src = redbuf + ((group * 2 + (slice >> 1)) * 32 + lane) * REDSL;
        #pragma unroll
        for (int k = 0; k < 16; k++) {
            skp[k] = add2(skp[k], src[k]);
            sap[k] = add2(sap[k], src[16 + k]);
        }
        float d0, d1; unpack2(src[32], d0, d1); den += d0;
    }
    __syncthreads();
    // round 2: slice 2 stores; slice 0 absorbs
    if (slice == 2) {
        u64* dst = redbuf + ((group * 2) * 32 + lane) * REDSL;
        #pragma unroll
        for (int k = 0; k < 16; k++) { dst[k] = skp[k]; dst[16 + k] = sap[k]; }
        dst[32] = pack2(den, 0.f);
    }
    __syncthreads();
    if (slice == 0) {
        u64* src = redbuf + ((group * 2) * 32 + lane) * REDSL;
        #pragma unroll
        for (int k = 0; k < 16; k++) {
            skp[k] = add2(skp[k], src[k]);
            sap[k] = add2(sap[k], src[16 + k]);
        }
        float d0, d1; unpack2(src[32], d0, d1); den += d0;

        // global accumulation: fire-and-forget RED
        float* gp = g_sum + b * 65;
        #pragma unroll
        for (int k = 0; k < 16; k++) {
            float v0, v1;
            unpack2(skp[k], v0, v1);
            redg_f32(gp + 2 * k, v0);
            redg_f32(gp + 2 * k + 1, v1);
            unpack2(sap[k], v0, v1);
            redg_f32(gp + 32 + 2 * k, v0);
            redg_f32(gp + 32 + 2 * k + 1, v1);
        }
        redg_f32(gp + 64, den);
    }

    // ---------------- last CTA finalizes --------------------------------------
    __threadfence();                            // all threads: order my REDGs
    __syncthreads();                            // CTA-wide: everyone fenced
    if (tid == 0) {
        unsigned old = atomicAdd(&g_ctr, 1u);
        sLast = (old == gridDim.x - 1) ? 1u : 0u;
    }
    __syncthreads();
    if (sLast) {
        __threadfence();
        volatile const float* vs = g_sum;
        for (int e = tid; e < NB * ND; e += 512) {
            int bb = e >> 5, i = e & 31;
            float sk = vs[bb * 65 + i];
            float sa = vs[bb * 65 + 32 + i];
            float dn = vs[bb * 65 + 64];
            out[e] = fmaf(X[e], sk, sa) / dn;
        }
        __syncthreads();                        // all reads done before re-zero
        for (int e = tid; e < NB * 65; e += 512) g_sum[e] = 0.f;
        __threadfence();
        if (tid == 0) g_ctr = 0u;
    }
}

// ---------------- launch ------------------------------------------------------
extern "C" void kernel_launch(void* const* d_in, const int* in_sizes, int n_in,
                              void* d_out, int out_size) {
    const float* X   = (const float*)d_in[0];
    const float* t   = (const float*)d_in[1];
    const float* Mu0 = (const float*)d_in[2];
    const float* Mu1 = (const float*)d_in[3];
    const float* S0  = (const float*)d_in[4];
    const float* S1  = (const float*)d_in[5];
    const float* Lam = (const float*)d_in[6];
    float* out = (float*)d_out;

    cudaFuncSetAttribute(kfused, cudaFuncAttributeMaxDynamicSharedMemorySize, SMEMT);
    kfused<<<148, 512, SMEMT>>>(X, t, Mu0, Mu1, S0, S1, Lam, out);
}

// round 9
// speedup vs baseline: 1.0355x; 1.0355x over previous
#include <cuda_runtime.h>
#include <math.h>
#include <stdint.h>

#define NB    128
#define ND    32
#define NPAIR 16384
#define EPS2  0.25f
#define EPS4  0.0625f
#define PERC  111                        // pairs per CTA (ceil(16384/148))
#define RECF4 33                         // float4s per pair record
#define RECB  (RECF4*16)                 // 528 bytes
#define SRECB (PERC*RECB)                // 58608 B coefficient region
#define WTB   (4*PERC*32*4)              // 56832 B wt region [group][pair][lane]
#define REDB  (8*32*33*8)                // 67584 B reduction region (reuses wt? no, after)
#define SMEMT (SRECB + WTB)              // 115440 B total dynamic smem

typedef unsigned long long u64;

// ---------------- packed f32x2 helpers ---------------------------------------
__device__ __forceinline__ u64 pack2(float lo, float hi) {
    u64 r; asm("mov.b64 %0,{%1,%2};" : "=l"(r) : "f"(lo), "f"(hi)); return r;
}
__device__ __forceinline__ void unpack2(u64 v, float& lo, float& hi) {
    asm("mov.b64 {%0,%1},%2;" : "=f"(lo), "=f"(hi) : "l"(v));
}
__device__ __forceinline__ u64 fma2(u64 a, u64 b, u64 c) {
    u64 d; asm("fma.rn.f32x2 %0,%1,%2,%3;" : "=l"(d) : "l"(a), "l"(b), "l"(c)); return d;
}
__device__ __forceinline__ u64 add2(u64 a, u64 b) {
    u64 d; asm("add.rn.f32x2 %0,%1,%2;" : "=l"(d) : "l"(a), "l"(b)); return d;
}
__device__ __forceinline__ void lds_v2u64(uint32_t addr, u64& a, u64& b) {
    asm volatile("ld.shared.v2.u64 {%0,%1},[%2];" : "=l"(a), "=l"(b) : "r"(addr));
}
__device__ __forceinline__ uint32_t smem_u32(const void* p) {
    uint32_t a;
    asm("{ .reg .u64 t; cvta.to.shared.u64 t, %1; cvt.u32.u64 %0, t; }" : "=r"(a) : "l"(p));
    return a;
}
__device__ __forceinline__ void redg_f32(float* p, float v) {
    asm volatile("red.global.add.f32 [%0],%1;" :: "l"(p), "f"(v) : "memory");
}

// ---------------- device state ------------------------------------------------
__device__ float    g_sum[NB * 65];      // zero at load; last CTA re-zeroes
__device__ unsigned g_ctr;

// ---------------- fused kernel ------------------------------------------------
// grid 148, 512 threads, 1 CTA/SM. 16 warps = 4 batch-groups x 4 pair slices.
// Phase A : coefficient records into smem (once chip-wide per pair).
// Phase B1: wt = exp(logw)*lam per (pair, batch-lane) -> smem (xp live, no accums).
// Phase B2: accumulate sk/sa/den from wt + K/A (accums live, no xp).
// Phase C : STS.64 tree reduction -> REDG -> last-CTA finalize.
__global__ void __launch_bounds__(512, 1)
kfused(const float* __restrict__ X,
       const float* __restrict__ tptr,
       const float* __restrict__ Mu0,
       const float* __restrict__ Mu1,
       const float* __restrict__ S0,
       const float* __restrict__ S1,
       const float* __restrict__ Lam,
       float* __restrict__ out) {
    extern __shared__ __align__(16) float4 srec[];
    __shared__ unsigned sLast;

    const int tid  = threadIdx.x;
    const int lane = tid & 31;
    const int w    = tid >> 5;
    const int gx   = blockIdx.x;

    const int pbeg = gx * PERC;
    const int cnt  = min(PERC, NPAIR - pbeg);

    // ---------------- Phase A: inline coefficient prep (lane = dim) ----------
    {
        const float t = tptr[0];
        const float u = 1.f - t;
        const int n = lane;
        for (int local = w; local < cnt; local += 16) {
            int p = pbeg + local;
            int i = p >> 7, j = p & 127;

            float s0 = S0[i * ND + n];
            float s1 = S1[j * ND + n];
            float Ds = sqrtf(fmaf(4.f * s0, s1, EPS4));
            float Cs = 0.5f * (Ds - EPS2);
            float Sigma = u * u * s0 + t * t * s1 + 2.f * t * u * Cs + EPS2 * t * u;
            float St = (t * s1 + u * Cs) - (u * s0 + t * Cs) - EPS2 * t;

            float inv = __fdividef(1.0f, Sigma);
            float K   = St * inv;

            float m0  = Mu0[i * ND + n];
            float m1  = Mu1[j * ND + n];
            float Mut = fmaf(t, m1, u * m0);
            float v   = m1 - m0;

            float a  = -0.5f * inv;
            float bq = Mut * inv;
            float A  = fmaf(-K, Mut, v);

            float cterm = fmaf(a * Mut, Mut, -0.5f * __logf(Sigma));
            #pragma unroll
            for (int o = 16; o; o >>= 1)
                cterm += __shfl_xor_sync(0xffffffffu, cterm, o);

            float aP = __shfl_xor_sync(0xffffffffu, a, 1);
            float bP = __shfl_xor_sync(0xffffffffu, bq, 1);
            float KP = __shfl_xor_sync(0xffffffffu, K, 1);
            float AP = __shfl_xor_sync(0xffffffffu, A, 1);

            float4* r4 = srec + local * RECF4;
            int k = n >> 1;
            if ((n & 1) == 0) r4[k]      = make_float4(a, aP, bq, bP);
            else              r4[16 + k] = make_float4(KP, K, AP, A);
            if (n == 0)       r4[32]     = make_float4(cterm, __ldg(Lam + p), 0.f, 0.f);
        }
    }
    __syncthreads();

    const int group = w >> 2;                   // 0..3: 32-batch group
    const int slice = w & 3;                    // pair slice among 4 warps
    const int b     = group * 32 + lane;
    const uint32_t sbase  = smem_u32(srec);
    const uint32_t wtbase = sbase + SRECB + (uint32_t)(group * PERC) * 128 + lane * 4;

    // ---------------- Phase B1: weights (xp live, no accumulators) ------------
    {
        u64 xp[16];
        const float4* X4 = reinterpret_cast<const float4*>(X + b * ND);
        #pragma unroll
        for (int q = 0; q < 8; q++) {
            float4 xv = X4[q];
            xp[2 * q]     = pack2(xv.x, xv.y);
            xp[2 * q + 1] = pack2(xv.z, xv.w);
        }
        const u64 zz = pack2(0.f, 0.f);

        for (int j = slice; j < cnt; j += 4) {
            uint32_t rec = sbase + j * RECB;
            u64 lw0 = zz, lw1 = zz;
            #pragma unroll
            for (int k = 0; k < 16; k += 2) {
                u64 ap, bp;
                lds_v2u64(rec + k * 16, ap, bp);
                lw0 = fma2(xp[k], fma2(ap, xp[k], bp), lw0);
                u64 ap1, bp1;
                lds_v2u64(rec + (k + 1) * 16, ap1, bp1);
                lw1 = fma2(xp[k + 1], fma2(ap1, xp[k + 1], bp1), lw1);
            }
            float cl0, cl1;
            asm volatile("ld.shared.v2.f32 {%0,%1},[%2];"
                         : "=f"(cl0), "=f"(cl1) : "r"(rec + 512));
            float a0, a1, b0v, b1v;
            unpack2(lw0, a0, a1);
            unpack2(lw1, b0v, b1v);
            float lw = (a0 + a1) + (b0v + b1v) + cl0;
            lw = fminf(fmaxf(lw, -50.f), 50.f);
            float wt = __expf(lw) * cl1;
            asm volatile("st.shared.f32 [%0],%1;" :: "r"(wtbase + j * 128), "f"(wt) : "memory");
        }
    }

    // ---------------- Phase B2: accumulate (no xp live) -----------------------
    u64 skp[16], sap[16];
    const u64 zz = pack2(0.f, 0.f);
    #pragma unroll
    for (int k = 0; k < 16; k++) { skp[k] = zz; sap[k] = zz; }
    float den = 0.f;

    for (int j = slice; j < cnt; j += 4) {
        uint32_t rec = sbase + j * RECB + 256;
        float wt;
        asm volatile("ld.shared.f32 %0,[%1];" : "=f"(wt) : "r"(wtbase + j * 128));
        den += wt;
        u64 wtp = pack2(wt, wt);
        #pragma unroll
        for (int k = 0; k < 16; k++) {
            u64 kp, Ap;
            lds_v2u64(rec + k * 16, kp, Ap);
            skp[k] = fma2(wtp, kp, skp[k]);
            sap[k] = fma2(wtp, Ap, sap[k]);
        }
    }

    // ---------------- Phase C: tree reduction (reuse record smem) -------------
    __syncthreads();                            // done reading coefficients
    u64* redbuf = reinterpret_cast<u64*>(srec); // 8 slots x 32 lanes x 33 u64

    if (slice & 1) {
        u64* dst = redbuf + ((group * 2 + (slice >> 1)) * 32 + lane) * 33;
        #pragma unroll
        for (int k = 0; k < 16; k++) { dst[k] = skp[k]; dst[16 + k] = sap[k]; }
        dst[32] = pack2(den, 0.f);
    }
    __syncthreads();
    if ((slice & 1) == 0) {
        u64* src = redbuf + ((group * 2 + (slice >> 1)) * 32 + lane) * 33;
        #pragma unroll
        for (int k = 0; k < 16; k++) {
            skp[k] = add2(skp[k], src[k]);
            sap[k] = add2(sap[k], src[16 + k]);
        }
        float d0, d1; unpack2(src[32], d0, d1); den += d0;
    }
    __syncthreads();
    if (slice == 2) {
        u64* dst = redbuf + ((group * 2) * 32 + lane) * 33;
        #pragma unroll
        for (int k = 0; k < 16; k++) { dst[k] = skp[k]; dst[16 + k] = sap[k]; }
        dst[32] = pack2(den, 0.f);
    }
    __syncthreads();
    if (slice == 0) {
        u64* src = redbuf + ((group * 2) * 32 + lane) * 33;
        #pragma unroll
        for (int k = 0; k < 16; k++) {
            skp[k] = add2(skp[k], src[k]);
            sap[k] = add2(sap[k], src[16 + k]);
        }
        float d0, d1; unpack2(src[32], d0, d1); den += d0;

        float* gp = g_sum + b * 65;
        #pragma unroll
        for (int k = 0; k < 16; k++) {
            float v0, v1;
            unpack2(skp[k], v0, v1);
            redg_f32(gp + 2 * k, v0);
            redg_f32(gp + 2 * k + 1, v1);
            unpack2(sap[k], v0, v1);
            redg_f32(gp + 32 + 2 * k, v0);
            redg_f32(gp + 32 + 2 * k + 1, v1);
        }
        redg_f32(gp + 64, den);
    }

    // ---------------- last CTA finalizes --------------------------------------
    __threadfence();
    __syncthreads();
    if (tid == 0) {
        unsigned old = atomicAdd(&g_ctr, 1u);
        sLast = (old == gridDim.x - 1) ? 1u : 0u;
    }
    __syncthreads();
    if (sLast) {
        __threadfence();
        volatile const float* vs = g_sum;
        for (int e = tid; e < NB * ND; e += 512) {
            int bb = e >> 5, i = e & 31;
            float sk = vs[bb * 65 + i];
            float sa = vs[bb * 65 + 32 + i];
            float dn = vs[bb * 65 + 64];
            out[e] = fmaf(X[e], sk, sa) / dn;
        }
        __syncthreads();
        for (int e = tid; e < NB * 65; e += 512) g_sum[e] = 0.f;
        __threadfence();
        if (tid == 0) g_ctr = 0u;
    }
}

// ---------------- launch ------------------------------------------------------
extern "C" void kernel_launch(void* const* d_in, const int* in_sizes, int n_in,
                              void* d_out, int out_size) {
    const float* X   = (const float*)d_in[0];
    const float* t   = (const float*)d_in[1];
    const float* Mu0 = (const float*)d_in[2];
    const float* Mu1 = (const float*)d_in[3];
    const float* S0  = (const float*)d_in[4];
    const float* S1  = (const float*)d_in[5];
    const float* Lam = (const float*)d_in[6];
    float* out = (float*)d_out;

    cudaFuncSetAttribute(kfused, cudaFuncAttributeMaxDynamicSharedMemorySize, SMEMT);
    kfused<<<148, 512, SMEMT>>>(X, t, Mu0, Mu1, S0, S1, Lam, out);
}

// round 10
// speedup vs baseline: 1.0532x; 1.0171x over previous
#include <cuda_runtime.h>
#include <math.h>
#include <stdint.h>

#define NB    128
#define ND    32
#define NPAIR 16384
#define EPS2  0.25f
#define EPS4  0.0625f
#define PERC  111                        // pairs per CTA (ceil(16384/148))
#define RECF4 33                         // float4s per pair record
#define RECB  (RECF4*16)                 // 528 bytes
#define SRECB (PERC*RECB)                // 58608 B coefficient region
#define WTB   (4*PERC*32*4)              // 56832 B wt region [group][pair][lane]
#define SMEMT (SRECB + WTB)              // 115440 B total dynamic smem

typedef unsigned long long u64;

// ---------------- packed f32x2 helpers ---------------------------------------
__device__ __forceinline__ u64 pack2(float lo, float hi) {
    u64 r; asm("mov.b64 %0,{%1,%2};" : "=l"(r) : "f"(lo), "f"(hi)); return r;
}
__device__ __forceinline__ void unpack2(u64 v, float& lo, float& hi) {
    asm("mov.b64 {%0,%1},%2;" : "=f"(lo), "=f"(hi) : "l"(v));
}
__device__ __forceinline__ u64 fma2(u64 a, u64 b, u64 c) {
    u64 d; asm("fma.rn.f32x2 %0,%1,%2,%3;" : "=l"(d) : "l"(a), "l"(b), "l"(c)); return d;
}
__device__ __forceinline__ u64 add2(u64 a, u64 b) {
    u64 d; asm("add.rn.f32x2 %0,%1,%2;" : "=l"(d) : "l"(a), "l"(b)); return d;
}
__device__ __forceinline__ void lds_v2u64(uint32_t addr, u64& a, u64& b) {
    asm volatile("ld.shared.v2.u64 {%0,%1},[%2];" : "=l"(a), "=l"(b) : "r"(addr));
}
__device__ __forceinline__ uint32_t smem_u32(const void* p) {
    uint32_t a;
    asm("{ .reg .u64 t; cvta.to.shared.u64 t, %1; cvt.u32.u64 %0, t; }" : "=r"(a) : "l"(p));
    return a;
}
__device__ __forceinline__ void redg_f32(float* p, float v) {
    asm volatile("red.global.add.f32 [%0],%1;" :: "l"(p), "f"(v) : "memory");
}

// ---------------- device state ------------------------------------------------
__device__ float    g_sum[NB * 65];      // zero at load; last CTA re-zeroes
__device__ unsigned g_ctr;

// ---------------- fused kernel ------------------------------------------------
// grid 148, 1024 threads, 1 CTA/SM, 32 lightweight warps (<=64 regs/thread).
// Phase A : coefficient records into smem (lane = dim, warp = pair stride 32).
// Phase B1: 32 warps = 4 batch-groups x 8 pair-slices -> wt to smem.
// Phase B2: 32 warps = 4 groups x 2 dim-halves x 4 slices -> sk/sa[8] each.
// Phase C : 3-store tree reduction per (group,half) -> REDG -> last-CTA finalize.
__global__ void __launch_bounds__(1024, 1)
kfused(const float* __restrict__ X,
       const float* __restrict__ tptr,
       const float* __restrict__ Mu0,
       const float* __restrict__ Mu1,
       const float* __restrict__ S0,
       const float* __restrict__ S1,
       const float* __restrict__ Lam,
       float* __restrict__ out) {
    extern __shared__ __align__(16) float4 srec[];
    __shared__ unsigned sLast;

    const int tid  = threadIdx.x;
    const int lane = tid & 31;
    const int w    = tid >> 5;
    const int gx   = blockIdx.x;

    const int pbeg = gx * PERC;
    const int cnt  = min(PERC, NPAIR - pbeg);

    // ---------------- Phase A: inline coefficient prep (lane = dim) ----------
    {
        const float t = tptr[0];
        const float u = 1.f - t;
        const int n = lane;
        for (int local = w; local < cnt; local += 32) {
            int p = pbeg + local;
            int i = p >> 7, j = p & 127;

            float s0 = S0[i * ND + n];
            float s1 = S1[j * ND + n];
            float Ds = sqrtf(fmaf(4.f * s0, s1, EPS4));
            float Cs = 0.5f * (Ds - EPS2);
            float Sigma = u * u * s0 + t * t * s1 + 2.f * t * u * Cs + EPS2 * t * u;
            float St = (t * s1 + u * Cs) - (u * s0 + t * Cs) - EPS2 * t;

            float inv = __fdividef(1.0f, Sigma);
            float K   = St * inv;

            float m0  = Mu0[i * ND + n];
            float m1  = Mu1[j * ND + n];
            float Mut = fmaf(t, m1, u * m0);
            float v   = m1 - m0;

            float a  = -0.5f * inv;
            float bq = Mut * inv;
            float A  = fmaf(-K, Mut, v);

            float cterm = fmaf(a * Mut, Mut, -0.5f * __logf(Sigma));
            #pragma unroll
            for (int o = 16; o; o >>= 1)
                cterm += __shfl_xor_sync(0xffffffffu, cterm, o);

            float aP = __shfl_xor_sync(0xffffffffu, a, 1);
            float bP = __shfl_xor_sync(0xffffffffu, bq, 1);
            float KP = __shfl_xor_sync(0xffffffffu, K, 1);
            float AP = __shfl_xor_sync(0xffffffffu, A, 1);

            float4* r4 = srec + local * RECF4;
            int k = n >> 1;
            if ((n & 1) == 0) r4[k]      = make_float4(a, aP, bq, bP);
            else              r4[16 + k] = make_float4(KP, K, AP, A);
            if (n == 0)       r4[32]     = make_float4(cterm, __ldg(Lam + p), 0.f, 0.f);
        }
    }
    __syncthreads();

    const int group = w >> 3;                   // 0..3 (B1 view)
    const uint32_t sbase = smem_u32(srec);

    // ---------------- Phase B1: weights (4 groups x 8 slices) -----------------
    {
        const int slice8 = w & 7;
        const int b1     = group * 32 + lane;
        const uint32_t wtb1 = sbase + SRECB + (uint32_t)(group * PERC) * 128 + lane * 4;

        u64 xp[16];
        const float4* X4 = reinterpret_cast<const float4*>(X + b1 * ND);
        #pragma unroll
        for (int q = 0; q < 8; q++) {
            float4 xv = X4[q];
            xp[2 * q]     = pack2(xv.x, xv.y);
            xp[2 * q + 1] = pack2(xv.z, xv.w);
        }
        const u64 zz = pack2(0.f, 0.f);

        for (int j = slice8; j < cnt; j += 8) {
            uint32_t rec = sbase + j * RECB;
            u64 lw0 = zz, lw1 = zz;
            #pragma unroll
            for (int k = 0; k < 16; k += 2) {
                u64 ap, bp;
                lds_v2u64(rec + k * 16, ap, bp);
                lw0 = fma2(xp[k], fma2(ap, xp[k], bp), lw0);
                u64 ap1, bp1;
                lds_v2u64(rec + (k + 1) * 16, ap1, bp1);
                lw1 = fma2(xp[k + 1], fma2(ap1, xp[k + 1], bp1), lw1);
            }
            float cl0, cl1;
            asm volatile("ld.shared.v2.f32 {%0,%1},[%2];"
                         : "=f"(cl0), "=f"(cl1) : "r"(rec + 512));
            float a0, a1, b0v, b1v;
            unpack2(lw0, a0, a1);
            unpack2(lw1, b0v, b1v);
            float lw = (a0 + a1) + (b0v + b1v) + cl0;
            lw = fminf(fmaxf(lw, -50.f), 50.f);
            float wt = __expf(lw) * cl1;
            asm volatile("st.shared.f32 [%0],%1;" :: "r"(wtb1 + j * 128), "f"(wt) : "memory");
        }
    }
    __syncthreads();                            // wt complete for all groups

    // ---------------- Phase B2: accumulate (4 groups x 2 halves x 4 slices) ---
    const int half   = w & 1;                   // dim half
    const int slice4 = (w >> 1) & 3;            // pair slice
    const int b      = group * 32 + lane;
    const uint32_t wtbase = sbase + SRECB + (uint32_t)(group * PERC) * 128 + lane * 4;
    const uint32_t kaoff  = 256 + half * 128;   // 8 x 16B of this half's K/A

    u64 skp[8], sap[8];
    const u64 zz = pack2(0.f, 0.f);
    #pragma unroll
    for (int k = 0; k < 8; k++) { skp[k] = zz; sap[k] = zz; }
    float den = 0.f;

    for (int j = slice4; j < cnt; j += 4) {
        uint32_t rec = sbase + j * RECB + kaoff;
        float wt;
        asm volatile("ld.shared.f32 %0,[%1];" : "=f"(wt) : "r"(wtbase + j * 128));
        den += wt;
        u64 wtp = pack2(wt, wt);
        #pragma unroll
        for (int k = 0; k < 8; k++) {
            u64 kp, Ap;
            lds_v2u64(rec + k * 16, kp, Ap);
            skp[k] = fma2(wtp, kp, skp[k]);
            sap[k] = fma2(wtp, Ap, sap[k]);
        }
    }

    // ---------------- Phase C: tree reduction (reuse all smem) ----------------
    __syncthreads();                            // done reading records + wt
    u64* redbuf = reinterpret_cast<u64*>(srec); // 24 slots x 32 lanes x 17 u64

    const int g2h = group * 2 + half;           // 0..7
    if (slice4 != 0) {
        u64* dst = redbuf + ((g2h * 3 + (slice4 - 1)) * 32 + lane) * 17;
        #pragma unroll
        for (int k = 0; k < 8; k++) { dst[k] = skp[k]; dst[8 + k] = sap[k]; }
        dst[16] = pack2(den, 0.f);
    }
    __syncthreads();
    if (slice4 == 0) {
        #pragma unroll
        for (int r = 0; r < 3; r++) {
            u64* src = redbuf + ((g2h * 3 + r) * 32 + lane) * 17;
            #pragma unroll
            for (int k = 0; k < 8; k++) {
                skp[k] = add2(skp[k], src[k]);
                sap[k] = add2(sap[k], src[8 + k]);
            }
            float d0, d1; unpack2(src[16], d0, d1); den += d0;
        }

        // global accumulation: fire-and-forget RED (dims of this half)
        float* gp = g_sum + b * 65;
        #pragma unroll
        for (int k = 0; k < 8; k++) {
            float v0, v1;
            unpack2(skp[k], v0, v1);
            redg_f32(gp + half * 16 + 2 * k, v0);
            redg_f32(gp + half * 16 + 2 * k + 1, v1);
            unpack2(sap[k], v0, v1);
            redg_f32(gp + 32 + half * 16 + 2 * k, v0);
            redg_f32(gp + 32 + half * 16 + 2 * k + 1, v1);
        }
        if (half == 0) redg_f32(gp + 64, den);
    }

    // ---------------- last CTA finalizes --------------------------------------
    __threadfence();
    __syncthreads();
    if (tid == 0) {
        unsigned old = atomicAdd(&g_ctr, 1u);
        sLast = (old == gridDim.x - 1) ? 1u : 0u;
    }
    __syncthreads();
    if (sLast) {
        __threadfence();
        volatile const float* vs = g_sum;
        for (int e = tid; e < NB * ND; e += 1024) {
            int bb = e >> 5, i = e & 31;
            float sk = vs[bb * 65 + i];
            float sa = vs[bb * 65 + 32 + i];
            float dn = vs[bb * 65 + 64];
            out[e] = fmaf(X[e], sk, sa) / dn;
        }
        __syncthreads();
        for (int e = tid; e < NB * 65; e += 1024) g_sum[e] = 0.f;
        __threadfence();
        if (tid == 0) g_ctr = 0u;
    }
}

// ---------------- launch ------------------------------------------------------
extern "C" void kernel_launch(void* const* d_in, const int* in_sizes, int n_in,
                              void* d_out, int out_size) {
    const float* X   = (const float*)d_in[0];
    const float* t   = (const float*)d_in[1];
    const float* Mu0 = (const float*)d_in[2];
    const float* Mu1 = (const float*)d_in[3];
    const float* S0  = (const float*)d_in[4];
    const float* S1  = (const float*)d_in[5];
    const float* Lam = (const float*)d_in[6];
    float* out = (float*)d_out;

    cudaFuncSetAttribute(kfused, cudaFuncAttributeMaxDynamicSharedMemorySize, SMEMT);
    kfused<<<148, 1024, SMEMT>>>(X, t, Mu0, Mu1, S0, S1, Lam, out);
}